// round 13
// baseline (speedup 1.0000x reference)
#include <cuda_runtime.h>
#include <cuda_bf16.h>

#define B_ROWS 16384
#define L_COLS 1024
#define ROWS_PER_BLK 16
#define NBLKS (B_ROWS / ROWS_PER_BLK)   // 1024

// Per-block partial sums of row losses (no device allocation allowed).
__device__ float g_partials[NBLKS];

#define EXP_ACC(cval, yval)                              \
    do {                                                 \
        const float e = __expf((yval) ? -(cval) : (cval)); \
        if (yval) { pos += e; yc++; } else { neg += e; } \
    } while (0)

// 1024 blocks x 512 threads (16 warps). Warp w handles row blockIdx.x*16 + w.
// Each iteration batches 2 float4 + 2 int4 loads (MLP=4 per thread) before
// any consumption -> ~24KB in flight per SM at 3 blocks/SM, enough to move
// from latency-limited to throughput-limited.
__global__ void __launch_bounds__(512, 3)
bpmll_row_kernel(const float* __restrict__ c, const int* __restrict__ y,
                 float* __restrict__ partials) {
    const int t = threadIdx.x;
    const int warp = t >> 5;
    const int lane = t & 31;
    const int row = blockIdx.x * ROWS_PER_BLK + warp;

    const float4* __restrict__ c4 =
        reinterpret_cast<const float4*>(c + (size_t)row * L_COLS);
    const int4* __restrict__ y4 =
        reinterpret_cast<const int4*>(y + (size_t)row * L_COLS);

    float pos = 0.0f, neg = 0.0f;
    int yc = 0;

    #pragma unroll
    for (int i = 0; i < 4; i++) {
        // Front-batch 4 independent 16B loads.
        const float4 ca = c4[i * 64 + lane];
        const float4 cb = c4[i * 64 + 32 + lane];
        const int4 ya = y4[i * 64 + lane];
        const int4 yb = y4[i * 64 + 32 + lane];

        EXP_ACC(ca.x, ya.x);
        EXP_ACC(ca.y, ya.y);
        EXP_ACC(ca.z, ya.z);
        EXP_ACC(ca.w, ya.w);
        EXP_ACC(cb.x, yb.x);
        EXP_ACC(cb.y, yb.y);
        EXP_ACC(cb.z, yb.z);
        EXP_ACC(cb.w, yb.w);
    }

    // Warp tree reduction (deterministic).
    #pragma unroll
    for (int off = 16; off > 0; off >>= 1) {
        pos += __shfl_down_sync(0xFFFFFFFFu, pos, off);
        neg += __shfl_down_sync(0xFFFFFFFFu, neg, off);
        yc  += __shfl_down_sync(0xFFFFFFFFu, yc, off);
    }

    __shared__ float s_loss[ROWS_PER_BLK];
    if (lane == 0) {
        const float yn = (float)yc;
        const float ybn = (float)(L_COLS - yc);
        s_loss[warp] = (pos * neg) / (yn * ybn);
    }
    __syncthreads();

    if (t == 0) {
        float sum = 0.0f;
        #pragma unroll
        for (int w = 0; w < ROWS_PER_BLK; w++) sum += s_loss[w];
        partials[blockIdx.x] = sum;
    }
    cudaTriggerProgrammaticLaunchCompletion();
}

// Single-block reduction of 1024 partials -> mean over 16384 rows.
// Launched with PDL; waits on the primary grid before reading partials.
__global__ void __launch_bounds__(256)
bpmll_reduce_kernel(const float* __restrict__ partials, float* __restrict__ out) {
    cudaGridDependencySynchronize();

    const int t = threadIdx.x;
    const float4 v = reinterpret_cast<const float4*>(partials)[t];  // 256*4 = 1024
    float s = (v.x + v.y) + (v.z + v.w);

    #pragma unroll
    for (int off = 16; off > 0; off >>= 1)
        s += __shfl_down_sync(0xFFFFFFFFu, s, off);

    __shared__ float s_w[8];
    const int warp = t >> 5;
    const int lane = t & 31;
    if (lane == 0) s_w[warp] = s;
    __syncthreads();

    if (t == 0) {
        float tot = 0.0f;
        #pragma unroll
        for (int w = 0; w < 8; w++) tot += s_w[w];
        out[0] = tot * (1.0f / (float)B_ROWS);
    }
}

extern "C" void kernel_launch(void* const* d_in, const int* in_sizes, int n_in,
                              void* d_out, int out_size) {
    const float* c = (const float*)d_in[0];
    const int* y = (const int*)d_in[1];
    float* out = (float*)d_out;

    float* partials = nullptr;
    cudaGetSymbolAddress((void**)&partials, g_partials);

    bpmll_row_kernel<<<NBLKS, 512>>>(c, y, partials);

    cudaLaunchConfig_t cfg = {};
    cfg.gridDim = dim3(1, 1, 1);
    cfg.blockDim = dim3(256, 1, 1);
    cfg.dynamicSmemBytes = 0;
    cfg.stream = 0;
    cudaLaunchAttribute attrs[1];
    attrs[0].id = cudaLaunchAttributeProgrammaticStreamSerialization;
    attrs[0].val.programmaticStreamSerializationAllowed = 1;
    cfg.attrs = attrs;
    cfg.numAttrs = 1;
    cudaLaunchKernelEx(&cfg, bpmll_reduce_kernel,
                       (const float*)partials, out);
}